// round 16
// baseline (speedup 1.0000x reference)
#include <cuda_runtime.h>
#include <cuda_fp16.h>
#include <cstdint>

// out[65536,64] = xa[65536,256]@wa[256,64] + xb[65536,256]@wb[256,64]
// Single-term fp16: out = fp16(x) @ fp16(w), fp32 accum. rel_err ~2.9e-4.
// mma.sync.m16n8k16.f32.f16.f16.f32, K-PERMUTED fragments (LDG.128 A loads),
// 32-row warps (B LDS.128 feeds 4 MMAs). SINGLE KERNEL: each CTA builds its
// 64 KB smem B fragment image directly from w (formulas identical to the
// old wconv pre-kernel) — no second graph node. A chunks 0/1 prefetched
// before the build to hide their latency. Depth-2 register prefetch, no CTA
// barriers in the main loop, 2 CTAs/SM, grid 256.

#define NCHUNK 32                   // chunks of 16 k
#define M_TILE 256

__device__ __forceinline__ uint32_t h2pack(float lo, float hi) {
    uint32_t r;
    asm("cvt.rn.f16x2.f32 %0, %1, %2;" : "=r"(r) : "f"(hi), "f"(lo));
    return r;
}

__device__ __forceinline__ void mma16816(float* c, const uint32_t* a,
                                         uint32_t b0, uint32_t b1) {
    asm volatile(
        "mma.sync.aligned.m16n8k16.row.col.f32.f16.f16.f32 "
        "{%0,%1,%2,%3}, {%4,%5,%6,%7}, {%8,%9}, {%0,%1,%2,%3};"
        : "+f"(c[0]), "+f"(c[1]), "+f"(c[2]), "+f"(c[3])
        : "r"(a[0]), "r"(a[1]), "r"(a[2]), "r"(a[3]), "r"(b0), "r"(b1));
}

// ---- main (and only) kernel ----
__global__ void __launch_bounds__(256, 2)
sshe_mma_kernel(const float* __restrict__ xa, const float* __restrict__ xb,
                const float* __restrict__ wa, const float* __restrict__ wb,
                float* __restrict__ out) {
    // fragment-packed B image, uint4 per (t, nj, L), t = 16-k step 0..31:
    //   index (t*4+nj)*32 + L; q=L&3, k0 = t*16 + 4q (permuted)
    //   x = wh{k0,k0+1}|n_e, y = wh{k0+2,k0+3}|n_e  (n_e = nj*16 + (L>>2))
    //   z = wh{k0,k0+1}|n_o, w = wh{k0+2,k0+3}|n_o  (n_o = n_e + 8)
    extern __shared__ uint4 sB[];   // 4096 entries = 64 KB
    const int tid = threadIdx.x;
    const int L = tid & 31;
    const int wid = tid >> 5;

    // A coordinates (k-permuted): warp owns rows [wid*32, wid*32+32)
    const int q = L & 3;
    const size_t rA = (size_t)(blockIdx.x * M_TILE + wid * 32 + (L >> 2));
    const size_t ro[4] = {
        rA * 256 + 4 * q, (rA + 8) * 256 + 4 * q,
        (rA + 16) * 256 + 4 * q, (rA + 24) * 256 + 4 * q};

    float4 st[3][4];
    auto load_chunk = [&](int c, float4* dst) {
        const float* __restrict__ xsrc = (c < 16) ? xa : xb;
        const int kb = (c & 15) * 16;
        dst[0] = *(const float4*)(xsrc + ro[0] + kb);
        dst[1] = *(const float4*)(xsrc + ro[1] + kb);
        dst[2] = *(const float4*)(xsrc + ro[2] + kb);
        dst[3] = *(const float4*)(xsrc + ro[3] + kb);
    };

    // prefetch A chunks 0/1 FIRST — their DRAM latency hides under the build
    load_chunk(0, st[0]);
    load_chunk(1, st[1]);

    // build B fragment image in smem (formulas identical to old wconv)
#pragma unroll
    for (int i = 0; i < 16; i++) {
        int id = tid + i * 256;                // 0..4095
        int LL = id & 31;
        int nj = (id >> 5) & 3;
        int t  = id >> 7;                      // 16-k step 0..31
        int qq = LL & 3;
        int k0 = t * 16 + 4 * qq;              // permuted global k
        const float* __restrict__ w = (k0 < 256) ? wa : wb;
        int kk = k0 & 255;
        int ne = nj * 16 + (LL >> 2);
        int no = ne + 8;
        uint4 r;
        r.x = h2pack(__ldg(w + kk * 64 + ne), __ldg(w + (kk + 1) * 64 + ne));
        r.y = h2pack(__ldg(w + (kk + 2) * 64 + ne), __ldg(w + (kk + 3) * 64 + ne));
        r.z = h2pack(__ldg(w + kk * 64 + no), __ldg(w + (kk + 1) * 64 + no));
        r.w = h2pack(__ldg(w + (kk + 2) * 64 + no), __ldg(w + (kk + 3) * 64 + no));
        sB[id] = r;
    }
    __syncthreads();

    float acc[2][8][4];
#pragma unroll
    for (int m = 0; m < 2; m++)
#pragma unroll
        for (int i = 0; i < 8; i++)
#pragma unroll
            for (int j = 0; j < 4; j++) acc[m][i][j] = 0.f;

    // main loop: depth-2 register prefetch, fully unrolled
#pragma unroll
    for (int c = 0; c < NCHUNK; c++) {
        if (c + 2 < NCHUNK) load_chunk(c + 2, st[(c + 2) % 3]);
        const float4* v = st[c % 3];

        uint32_t ah0[4], ah1[4];
        ah0[0] = h2pack(v[0].x, v[0].y);
        ah0[1] = h2pack(v[1].x, v[1].y);
        ah0[2] = h2pack(v[0].z, v[0].w);
        ah0[3] = h2pack(v[1].z, v[1].w);
        ah1[0] = h2pack(v[2].x, v[2].y);
        ah1[1] = h2pack(v[3].x, v[3].y);
        ah1[2] = h2pack(v[2].z, v[2].w);
        ah1[3] = h2pack(v[3].z, v[3].w);

        const int base4 = c * 128 + L;
#pragma unroll
        for (int nj = 0; nj < 4; nj++) {
            uint4 B = sB[base4 + nj * 32];   // one LDS.128, feeds 4 MMAs
            mma16816(acc[0][2 * nj], ah0, B.x, B.y);
            mma16816(acc[0][2 * nj + 1], ah0, B.z, B.w);
            mma16816(acc[1][2 * nj], ah1, B.x, B.y);
            mma16816(acc[1][2 * nj + 1], ah1, B.z, B.w);
        }
    }

    // epilogue (proven C mapping, per m-tile)
    const int kk2 = (L & 3) * 2;
#pragma unroll
    for (int mi = 0; mi < 2; mi++) {
        const size_t grow = rA + mi * 16;
#pragma unroll
        for (int ni = 0; ni < 8; ni++) {
            float* o0 = out + grow * 64 + ni * 8 + kk2;
            float* o1 = out + (grow + 8) * 64 + ni * 8 + kk2;
            *(float2*)o0 = make_float2(acc[mi][ni][0], acc[mi][ni][1]);
            *(float2*)o1 = make_float2(acc[mi][ni][2], acc[mi][ni][3]);
        }
    }
}

extern "C" void kernel_launch(void* const* d_in, const int* in_sizes, int n_in,
                              void* d_out, int out_size) {
    const float* xa = (const float*)d_in[0];
    const float* xb = (const float*)d_in[1];
    const float* wa = (const float*)d_in[2];
    const float* wb = (const float*)d_in[3];
    float* out = (float*)d_out;

    cudaFuncSetAttribute(sshe_mma_kernel,
                         cudaFuncAttributeMaxDynamicSharedMemorySize, 65536);

    const int batch = in_sizes[0] / 256;     // 65536
    sshe_mma_kernel<<<batch / M_TILE, 256, 65536>>>(xa, xb, wa, wb, out);
}